// round 10
// baseline (speedup 1.0000x reference)
#include <cuda_runtime.h>
#include <cuda_bf16.h>
#include <math.h>
#include <stdint.h>

#define H_DIM 4096
#define E_DIM 64
#define TOPK  8
#define BM    128                 // tokens per CTA
#define KC    64                  // K elements per chunk (= one accumulation segment)
#define NCHUNK (H_DIM / KC)       // 64
#define THREADS 512

#define A_PL  (BM * KC * 2)       // 16384 B per A bf16 plane
#define B_PL  (E_DIM * KC * 2)    // 8192  B per B bf16 plane
#define STAGE_SZ (3 * A_PL + 3 * B_PL)   // 73728 B
#define TILE_SZ (2 * STAGE_SZ)           // 147456 B
#define DYN_SZ (TILE_SZ + 256)

// Precomputed W bf16 planes, stored as ready-made swizzled smem images:
// wplanes[plane][chunk][8192 bytes] — GEMM cp.asyncs these straight in.
__device__ __align__(16) uint8_t wplanes[3][NCHUNK][B_PL];

__device__ __forceinline__ uint32_t s2u(const void* p) {
    uint32_t a;
    asm("{ .reg .u64 t; cvta.to.shared.u64 t, %1; cvt.u32.u64 %0, t; }" : "=r"(a) : "l"(p));
    return a;
}
__device__ __forceinline__ uint32_t swz(uint32_t b) { return b ^ ((b >> 3) & 0x70); }

// 3-way bf16 split of one float4: v = h + m + l  (verified R5/R8/R9)
__device__ __forceinline__ void split3(float4 v,
                                       uint32_t& h01, uint32_t& h23,
                                       uint32_t& m01, uint32_t& m23,
                                       uint32_t& l01, uint32_t& l23) {
    asm("cvt.rn.bf16x2.f32 %0, %1, %2;" : "=r"(h01) : "f"(v.y), "f"(v.x));
    asm("cvt.rn.bf16x2.f32 %0, %1, %2;" : "=r"(h23) : "f"(v.w), "f"(v.z));
    float h0 = __uint_as_float(h01 << 16);
    float h1 = __uint_as_float(h01 & 0xFFFF0000u);
    float h2 = __uint_as_float(h23 << 16);
    float h3 = __uint_as_float(h23 & 0xFFFF0000u);
    float r0 = v.x - h0, r1 = v.y - h1, r2 = v.z - h2, r3 = v.w - h3;
    asm("cvt.rn.bf16x2.f32 %0, %1, %2;" : "=r"(m01) : "f"(r1), "f"(r0));
    asm("cvt.rn.bf16x2.f32 %0, %1, %2;" : "=r"(m23) : "f"(r3), "f"(r2));
    float q0 = __uint_as_float(m01 << 16);
    float q1 = __uint_as_float(m01 & 0xFFFF0000u);
    float q2 = __uint_as_float(m23 << 16);
    float q3 = __uint_as_float(m23 & 0xFFFF0000u);
    asm("cvt.rn.bf16x2.f32 %0, %1, %2;" : "=r"(l01) : "f"(r1 - q1), "f"(r0 - q0));
    asm("cvt.rn.bf16x2.f32 %0, %1, %2;" : "=r"(l23) : "f"(r3 - q3), "f"(r2 - q2));
}

__device__ __forceinline__ void cvt_store3(float4 v, uint32_t hB, uint32_t mB, uint32_t lB,
                                           int row, int c4) {
    uint32_t h01, h23, m01, m23, l01, l23;
    split3(v, h01, h23, m01, m23, l01, l23);
    uint32_t off = swz((uint32_t)(row * 128 + c4 * 8));
    asm volatile("st.shared.v2.b32 [%0], {%1,%2};" :: "r"(hB + off), "r"(h01), "r"(h23));
    asm volatile("st.shared.v2.b32 [%0], {%1,%2};" :: "r"(mB + off), "r"(m01), "r"(m23));
    asm volatile("st.shared.v2.b32 [%0], {%1,%2};" :: "r"(lB + off), "r"(l01), "r"(l23));
}

// ---------------------------------------------------------------------------
// Pre-kernel: convert W[64,4096] into 3 swizzled bf16 plane images (once).
// ---------------------------------------------------------------------------
__global__ __launch_bounds__(256) void wconvert_kernel(const float* __restrict__ W) {
    int idx = blockIdx.x * blockDim.x + threadIdx.x;   // 0..65535
    int c4 = idx & 15;
    int e  = (idx >> 4) & 63;
    int ch = idx >> 10;                                // 0..63
    float4 v = *reinterpret_cast<const float4*>(W + (size_t)e * H_DIM + ch * KC + c4 * 4);
    uint32_t h01, h23, m01, m23, l01, l23;
    split3(v, h01, h23, m01, m23, l01, l23);
    uint32_t off = swz((uint32_t)(e * 128 + c4 * 8));
    *reinterpret_cast<uint2*>(&wplanes[0][ch][off]) = make_uint2(h01, h23);
    *reinterpret_cast<uint2*>(&wplanes[1][ch][off]) = make_uint2(m01, m23);
    *reinterpret_cast<uint2*>(&wplanes[2][ch][off]) = make_uint2(l01, l23);
}

__device__ __forceinline__ void cp16(uint32_t smem_dst, const void* gsrc) {
    asm volatile("cp.async.ca.shared.global [%0], [%1], 16;"
                 :: "r"(smem_dst), "l"(gsrc) : "memory");
}

__device__ __forceinline__ void load_chunkA(const float* __restrict__ A,
                                            int m0, int chunk, int tid, float4* ra) {
    const int k0 = chunk * KC;
    #pragma unroll
    for (int i = 0; i < 4; i++) {                 // 4*512 = 2048 = 128 rows x 16
        int idx = tid + i * THREADS;
        int row = idx >> 4;
        int c4  = idx & 15;
        ra[i] = *reinterpret_cast<const float4*>(A + (size_t)(m0 + row) * H_DIM + k0 + c4 * 4);
    }
}

__device__ __forceinline__ void ldsm4(uint32_t addr, uint32_t& r0, uint32_t& r1,
                                      uint32_t& r2, uint32_t& r3) {
    asm volatile("ldmatrix.sync.aligned.m8n8.x4.shared.b16 {%0,%1,%2,%3}, [%4];"
                 : "=r"(r0), "=r"(r1), "=r"(r2), "=r"(r3) : "r"(addr));
}

__device__ __forceinline__ void mma16816(float* d, const uint32_t* a, const uint32_t* b) {
    asm volatile(
        "mma.sync.aligned.m16n8k16.row.col.f32.bf16.bf16.f32 "
        "{%0,%1,%2,%3}, {%4,%5,%6,%7}, {%8,%9}, {%0,%1,%2,%3};"
        : "+f"(d[0]), "+f"(d[1]), "+f"(d[2]), "+f"(d[3])
        : "r"(a[0]), "r"(a[1]), "r"(a[2]), "r"(a[3]), "r"(b[0]), "r"(b[1]));
}

// ---------------------------------------------------------------------------
// HMMA bf16 3-way-split GEMM, segmented accumulation (numerics == R9).
// Pipelined: convert(c+1)/cp.async B(c+1) overlap compute(c).
// ---------------------------------------------------------------------------
__global__ __launch_bounds__(THREADS, 1) void router_gemm_tc(
    const float* __restrict__ A, float* __restrict__ logits)
{
    extern __shared__ char dsm[];
    const uint32_t base = (s2u(dsm) + 127u) & ~127u;
    uint32_t stage_base[2] = { base, base + STAGE_SZ };

    const int tid  = threadIdx.x;
    const int warp = tid >> 5;
    const int lane = tid & 31;
    const int m0   = blockIdx.x * BM;

    const int rg = warp >> 1;     // row group: rows rg*16 .. rg*16+15
    const int eh = warp & 1;      // expert half: experts eh*32 .. eh*32+31

    const int a_row   = rg * 16 + (lane & 15);
    const int a_khalf = lane >> 4;
    const uint32_t a_off0 = (uint32_t)(a_row * 128 + a_khalf * 16);
    const int b_rowl  = ((lane >> 4) << 3) + (lane & 7);
    const int b_khalf = (lane >> 3) & 1;
    const uint32_t b_off0 = (uint32_t)(b_rowl * 128 + b_khalf * 16 + eh * 2 * 2048);

    float accM[4][4];
    #pragma unroll
    for (int nt = 0; nt < 4; nt++)
        #pragma unroll
        for (int j = 0; j < 4; j++) accM[nt][j] = 0.f;

    // ---- prologue: stage chunk 0 ----
    float4 na[4];
    load_chunkA(A, m0, 0, tid, na);
    {
        const uint32_t aH = stage_base[0], aM = aH + A_PL, aL = aM + A_PL;
        const uint32_t bB = aL + A_PL;
        #pragma unroll
        for (int i = 0; i < 4; i++) {
            int idx = tid + i * THREADS;
            cvt_store3(na[i], aH, aM, aL, idx >> 4, idx & 15);
        }
        #pragma unroll
        for (int p = 0; p < 3; p++)
            cp16(bB + (uint32_t)p * B_PL + (uint32_t)tid * 16, &wplanes[p][0][tid * 16]);
        asm volatile("cp.async.commit_group;" ::: "memory");
    }
    load_chunkA(A, m0, 1, tid, na);
    asm volatile("cp.async.wait_group 0;" ::: "memory");
    __syncthreads();

    for (int chunk = 0; chunk < NCHUNK; ++chunk) {
        const int s  = chunk & 1;
        const int sn = s ^ 1;
        const uint32_t aH  = stage_base[s];
        const uint32_t bH  = aH + 3 * A_PL;
        const uint32_t bMp = bH + B_PL;
        const uint32_t bLp = bMp + B_PL;

        // stage chunk+1 into the other buffer (overlaps this chunk's mma)
        if (chunk + 1 < NCHUNK) {
            const uint32_t nH = stage_base[sn], nM = nH + A_PL, nL = nM + A_PL;
            const uint32_t nB = nL + A_PL;
            #pragma unroll
            for (int p = 0; p < 3; p++)
                cp16(nB + (uint32_t)p * B_PL + (uint32_t)tid * 16,
                     &wplanes[p][chunk + 1][tid * 16]);
            asm volatile("cp.async.commit_group;" ::: "memory");
            #pragma unroll
            for (int i = 0; i < 4; i++) {
                int idx = tid + i * THREADS;
                cvt_store3(na[i], nH, nM, nL, idx >> 4, idx & 15);
            }
            if (chunk + 2 < NCHUNK) load_chunkA(A, m0, chunk + 2, tid, na);
        }

        // ---- compute chunk from stage s ----
        float accS[4][4];
        #pragma unroll
        for (int nt = 0; nt < 4; nt++)
            #pragma unroll
            for (int j = 0; j < 4; j++) accS[nt][j] = 0.f;

        const uint32_t aMc = aH + A_PL, aLc = aMc + A_PL;
        #pragma unroll
        for (int ks = 0; ks < 4; ks++) {
            const uint32_t ka = (uint32_t)(ks * 32);
            uint32_t ah[4], am[4], al[4];
            ldsm4(aH  + swz(a_off0 + ka), ah[0], ah[1], ah[2], ah[3]);
            ldsm4(aMc + swz(a_off0 + ka), am[0], am[1], am[2], am[3]);
            ldsm4(aLc + swz(a_off0 + ka), al[0], al[1], al[2], al[3]);

            uint32_t bf[4][2];
            const uint32_t bo0 = swz(b_off0 + ka);
            const uint32_t bo1 = swz(b_off0 + 2048 + ka);

            ldsm4(bH + bo0, bf[0][0], bf[0][1], bf[1][0], bf[1][1]);
            ldsm4(bH + bo1, bf[2][0], bf[2][1], bf[3][0], bf[3][1]);
            #pragma unroll
            for (int nt = 0; nt < 4; nt++) mma16816(accS[nt], ah, bf[nt]);
            #pragma unroll
            for (int nt = 0; nt < 4; nt++) mma16816(accS[nt], am, bf[nt]);
            #pragma unroll
            for (int nt = 0; nt < 4; nt++) mma16816(accS[nt], al, bf[nt]);

            ldsm4(bMp + bo0, bf[0][0], bf[0][1], bf[1][0], bf[1][1]);
            ldsm4(bMp + bo1, bf[2][0], bf[2][1], bf[3][0], bf[3][1]);
            #pragma unroll
            for (int nt = 0; nt < 4; nt++) mma16816(accS[nt], ah, bf[nt]);
            #pragma unroll
            for (int nt = 0; nt < 4; nt++) mma16816(accS[nt], am, bf[nt]);

            ldsm4(bLp + bo0, bf[0][0], bf[0][1], bf[1][0], bf[1][1]);
            ldsm4(bLp + bo1, bf[2][0], bf[2][1], bf[3][0], bf[3][1]);
            #pragma unroll
            for (int nt = 0; nt < 4; nt++) mma16816(accS[nt], ah, bf[nt]);
        }

        #pragma unroll
        for (int nt = 0; nt < 4; nt++)
            #pragma unroll
            for (int j = 0; j < 4; j++) accM[nt][j] += accS[nt][j];

        if (chunk + 1 < NCHUNK)
            asm volatile("cp.async.wait_group 0;" ::: "memory");
        __syncthreads();
    }

    const int r0  = m0 + rg * 16 + (lane >> 2);
    const int col = eh * 32 + (lane & 3) * 2;
    #pragma unroll
    for (int nt = 0; nt < 4; nt++) {
        float* d0 = logits + (size_t)r0 * E_DIM + nt * 8 + col;
        float* d1 = logits + (size_t)(r0 + 8) * E_DIM + nt * 8 + col;
        *reinterpret_cast<float2*>(d0) = make_float2(accM[nt][0], accM[nt][1]);
        *reinterpret_cast<float2*>(d1) = make_float2(accM[nt][2], accM[nt][3]);
    }
}

// ---------------------------------------------------------------------------
// Kernel 2: top-8 + renormalized softmax scores (unchanged, verified)
// ---------------------------------------------------------------------------
__global__ __launch_bounds__(256) void topk_kernel(
    const float* __restrict__ logits,
    float* __restrict__ scores,
    float* __restrict__ indices, int T)
{
    const int warp = (int)((blockIdx.x * blockDim.x + threadIdx.x) >> 5);
    const int lane = threadIdx.x & 31;
    if (warp >= T) return;

    const float* lg = logits + (size_t)warp * E_DIM;
    float v0 = lg[lane];
    float v1 = lg[lane + 32];

    float topv[TOPK];
    int   topi[TOPK];

    #pragma unroll
    for (int r = 0; r < TOPK; r++) {
        bool p   = (v0 >= v1);
        float lv = p ? v0 : v1;
        int   li = p ? lane : lane + 32;
        #pragma unroll
        for (int off = 16; off > 0; off >>= 1) {
            float ov = __shfl_xor_sync(0xffffffffu, lv, off);
            int   oi = __shfl_xor_sync(0xffffffffu, li, off);
            if (ov > lv || (ov == lv && oi < li)) { lv = ov; li = oi; }
        }
        topv[r] = lv; topi[r] = li;
        if (li == lane)           v0 = -INFINITY;
        else if (li == lane + 32) v1 = -INFINITY;
    }

    if (lane == 0) {
        const float m = topv[0];
        float e[TOPK], s = 0.f;
        #pragma unroll
        for (int r = 0; r < TOPK; r++) { e[r] = expf(topv[r] - m); s += e[r]; }
        const float inv = 1.f / s;
        #pragma unroll
        for (int r = 0; r < TOPK; r++) {
            scores [(size_t)warp * TOPK + r] = e[r] * inv;
            indices[(size_t)warp * TOPK + r] = (float)topi[r];
        }
    }
}

// ---------------------------------------------------------------------------
extern "C" void kernel_launch(void* const* d_in, const int* in_sizes, int n_in,
                              void* d_out, int out_size)
{
    const float* hs = (const float*)d_in[0];   // hidden_states [T, 4096]
    const float* w  = (const float*)d_in[1];   // weight        [64, 4096]
    const int T = in_sizes[0] / H_DIM;

    float* out     = (float*)d_out;
    float* logits  = out;
    float* scores  = out + (size_t)T * E_DIM;
    float* indices = scores + (size_t)T * TOPK;

    wconvert_kernel<<<256, 256>>>(w);

    cudaFuncSetAttribute(router_gemm_tc, cudaFuncAttributeMaxDynamicSharedMemorySize, DYN_SZ);
    router_gemm_tc<<<T / BM, THREADS, DYN_SZ>>>(hs, logits);

    const int warps_per_block = 256 / 32;
    const int grid = (T + warps_per_block - 1) / warps_per_block;
    topk_kernel<<<grid, 256>>>(logits, scores, indices, T);
}

// round 11
// speedup vs baseline: 1.4398x; 1.4398x over previous
#include <cuda_runtime.h>
#include <cuda_fp16.h>
#include <math.h>
#include <stdint.h>

#define H_DIM 4096
#define E_DIM 64
#define TOPK  8
#define BM    128                 // tokens per CTA
#define KC    64                  // K elements per chunk (= one accumulation segment)
#define NCHUNK (H_DIM / KC)       // 64
#define THREADS 512

#define A_PL  (BM * KC * 2)       // 16384 B per A fp16 plane
#define B_PL  (E_DIM * KC * 2)    // 8192  B per B fp16 plane
#define STAGE_SZ (2 * A_PL + 2 * B_PL)   // 49152 B
#define TILE_SZ (2 * STAGE_SZ)           // 98304 B
#define DYN_SZ (TILE_SZ + 256)

#define W_SCALE   64.0f           // W pre-scale (2^6, exact)
#define OUT_SCALE 0.015625f       // 2^-6
#define LO_SCALE  2048.0f         // lo-plane pre-scale (2^11, exact)
#define LO_FOLD   4.8828125e-4f   // 2^-11

__device__ __forceinline__ uint32_t s2u(const void* p) {
    uint32_t a;
    asm("{ .reg .u64 t; cvta.to.shared.u64 t, %1; cvt.u32.u64 %0, t; }" : "=r"(a) : "l"(p));
    return a;
}
__device__ __forceinline__ uint32_t swz(uint32_t b) { return b ^ ((b >> 3) & 0x70); }

// fp16 2-way split of one float4: v*scale = h + l*2^-11 (l stored pre-scaled by 2^11).
// (v*scale - h) is exact (Sterbenz); *2^11 exact. Lo plane values stay normal fp16.
__device__ __forceinline__ void cvt_store2(float4 v, float scale,
                                           uint32_t hB, uint32_t lB, int row, int c4) {
    v.x *= scale; v.y *= scale; v.z *= scale; v.w *= scale;
    uint32_t h01, h23;
    asm("cvt.rn.f16x2.f32 %0, %1, %2;" : "=r"(h01) : "f"(v.y), "f"(v.x));
    asm("cvt.rn.f16x2.f32 %0, %1, %2;" : "=r"(h23) : "f"(v.w), "f"(v.z));
    float h0, h1, h2, h3;
    asm("{.reg .b16 lo,hi; mov.b32 {lo,hi}, %2; cvt.f32.f16 %0, lo; cvt.f32.f16 %1, hi;}"
        : "=f"(h0), "=f"(h1) : "r"(h01));
    asm("{.reg .b16 lo,hi; mov.b32 {lo,hi}, %2; cvt.f32.f16 %0, lo; cvt.f32.f16 %1, hi;}"
        : "=f"(h2), "=f"(h3) : "r"(h23));
    float r0 = (v.x - h0) * LO_SCALE, r1 = (v.y - h1) * LO_SCALE;
    float r2 = (v.z - h2) * LO_SCALE, r3 = (v.w - h3) * LO_SCALE;
    uint32_t l01, l23;
    asm("cvt.rn.f16x2.f32 %0, %1, %2;" : "=r"(l01) : "f"(r1), "f"(r0));
    asm("cvt.rn.f16x2.f32 %0, %1, %2;" : "=r"(l23) : "f"(r3), "f"(r2));
    uint32_t off = swz((uint32_t)(row * 128 + c4 * 8));
    asm volatile("st.shared.v2.b32 [%0], {%1,%2};" :: "r"(hB + off), "r"(h01), "r"(h23));
    asm volatile("st.shared.v2.b32 [%0], {%1,%2};" :: "r"(lB + off), "r"(l01), "r"(l23));
}

__device__ __forceinline__ void load_chunk(const float* __restrict__ A,
                                           const float* __restrict__ W,
                                           int m0, int chunk, int tid,
                                           float4* ra, float4* rb) {
    const int k0 = chunk * KC;
    #pragma unroll
    for (int i = 0; i < 4; i++) {                 // 4*512 = 2048 = 128 rows x 16
        int idx = tid + i * THREADS;
        int row = idx >> 4;
        int c4  = idx & 15;
        ra[i] = *reinterpret_cast<const float4*>(A + (size_t)(m0 + row) * H_DIM + k0 + c4 * 4);
    }
    #pragma unroll
    for (int i = 0; i < 2; i++) {                 // 2*512 = 1024 = 64 rows x 16
        int idx = tid + i * THREADS;
        int row = idx >> 4;
        int c4  = idx & 15;
        rb[i] = *reinterpret_cast<const float4*>(W + (size_t)row * H_DIM + k0 + c4 * 4);
    }
}

__device__ __forceinline__ void ldsm4(uint32_t addr, uint32_t& r0, uint32_t& r1,
                                      uint32_t& r2, uint32_t& r3) {
    asm volatile("ldmatrix.sync.aligned.m8n8.x4.shared.b16 {%0,%1,%2,%3}, [%4];"
                 : "=r"(r0), "=r"(r1), "=r"(r2), "=r"(r3) : "r"(addr));
}

__device__ __forceinline__ void mma16816(float* d, const uint32_t* a, const uint32_t* b) {
    asm volatile(
        "mma.sync.aligned.m16n8k16.row.col.f32.f16.f16.f32 "
        "{%0,%1,%2,%3}, {%4,%5,%6,%7}, {%8,%9}, {%0,%1,%2,%3};"
        : "+f"(d[0]), "+f"(d[1]), "+f"(d[2]), "+f"(d[3])
        : "r"(a[0]), "r"(a[1]), "r"(a[2]), "r"(a[3]), "r"(b[0]), "r"(b[1]));
}

// ---------------------------------------------------------------------------
// HMMA fp16 2-way-split GEMM (3 terms: hh, lh, hl), segmented accumulation.
// logits = (A @ (64*W)^T) * 2^-6.  Lo planes pre-scaled 2^11, folded * 2^-11.
// ---------------------------------------------------------------------------
__global__ __launch_bounds__(THREADS, 1) void router_gemm_tc(
    const float* __restrict__ A, const float* __restrict__ W,
    float* __restrict__ logits)
{
    extern __shared__ char dsm[];
    const uint32_t base = (s2u(dsm) + 127u) & ~127u;
    uint32_t stage_base[2] = { base, base + STAGE_SZ };

    const int tid  = threadIdx.x;
    const int warp = tid >> 5;
    const int lane = tid & 31;
    const int m0   = blockIdx.x * BM;

    const int rg = warp >> 1;     // row group: rows rg*16 .. rg*16+15
    const int eh = warp & 1;      // expert half: experts eh*32 .. eh*32+31

    const int a_row   = rg * 16 + (lane & 15);
    const int a_khalf = lane >> 4;
    const uint32_t a_off0 = (uint32_t)(a_row * 128 + a_khalf * 16);
    const int b_rowl  = ((lane >> 4) << 3) + (lane & 7);
    const int b_khalf = (lane >> 3) & 1;
    const uint32_t b_off0 = (uint32_t)(b_rowl * 128 + b_khalf * 16 + eh * 2 * 2048);

    float accM[4][4];
    #pragma unroll
    for (int nt = 0; nt < 4; nt++)
        #pragma unroll
        for (int j = 0; j < 4; j++) accM[nt][j] = 0.f;

    float4 na[4], nb[2];
    load_chunk(A, W, m0, 0, tid, na, nb);

    for (int chunk = 0; chunk < NCHUNK; ++chunk) {
        const int s = chunk & 1;
        const uint32_t aH = stage_base[s];
        const uint32_t aL = aH + A_PL;
        const uint32_t bH = aL + A_PL;
        const uint32_t bL = bH + B_PL;

        // convert + store current registers, THEN refill (register WAR is free)
        #pragma unroll
        for (int i = 0; i < 4; i++) {
            int idx = tid + i * THREADS;
            cvt_store2(na[i], 1.0f, aH, aL, idx >> 4, idx & 15);
        }
        #pragma unroll
        for (int i = 0; i < 2; i++) {
            int idx = tid + i * THREADS;
            cvt_store2(nb[i], W_SCALE, bH, bL, idx >> 4, idx & 15);
        }
        if (chunk + 1 < NCHUNK) load_chunk(A, W, m0, chunk + 1, tid, na, nb);
        __syncthreads();

        // fresh segment accumulators: accS0 = hh terms, accS1 = (lh + hl)*2^11
        float accS0[4][4], accS1[4][4];
        #pragma unroll
        for (int nt = 0; nt < 4; nt++)
            #pragma unroll
            for (int j = 0; j < 4; j++) { accS0[nt][j] = 0.f; accS1[nt][j] = 0.f; }

        #pragma unroll
        for (int ks = 0; ks < 4; ks++) {
            const uint32_t ka = (uint32_t)(ks * 32);
            uint32_t ah[4], al[4];
            ldsm4(aH + swz(a_off0 + ka), ah[0], ah[1], ah[2], ah[3]);
            ldsm4(aL + swz(a_off0 + ka), al[0], al[1], al[2], al[3]);

            uint32_t bf[4][2];
            const uint32_t bo0 = swz(b_off0 + ka);
            const uint32_t bo1 = swz(b_off0 + 2048 + ka);

            // B hi plane: hh -> accS0, lh -> accS1
            ldsm4(bH + bo0, bf[0][0], bf[0][1], bf[1][0], bf[1][1]);
            ldsm4(bH + bo1, bf[2][0], bf[2][1], bf[3][0], bf[3][1]);
            #pragma unroll
            for (int nt = 0; nt < 4; nt++) mma16816(accS0[nt], ah, bf[nt]);
            #pragma unroll
            for (int nt = 0; nt < 4; nt++) mma16816(accS1[nt], al, bf[nt]);

            // B lo plane: hl -> accS1
            ldsm4(bL + bo0, bf[0][0], bf[0][1], bf[1][0], bf[1][1]);
            ldsm4(bL + bo1, bf[2][0], bf[2][1], bf[3][0], bf[3][1]);
            #pragma unroll
            for (int nt = 0; nt < 4; nt++) mma16816(accS1[nt], ah, bf[nt]);
        }

        // fold segment: accM += accS0 + accS1 * 2^-11   (RN fp32)
        #pragma unroll
        for (int nt = 0; nt < 4; nt++)
            #pragma unroll
            for (int j = 0; j < 4; j++)
                accM[nt][j] += fmaf(accS1[nt][j], LO_FOLD, accS0[nt][j]);
    }

    // epilogue: undo W pre-scale (exact *2^-6)
    const int r0  = m0 + rg * 16 + (lane >> 2);
    const int col = eh * 32 + (lane & 3) * 2;
    #pragma unroll
    for (int nt = 0; nt < 4; nt++) {
        float* d0 = logits + (size_t)r0 * E_DIM + nt * 8 + col;
        float* d1 = logits + (size_t)(r0 + 8) * E_DIM + nt * 8 + col;
        *reinterpret_cast<float2*>(d0) =
            make_float2(accM[nt][0] * OUT_SCALE, accM[nt][1] * OUT_SCALE);
        *reinterpret_cast<float2*>(d1) =
            make_float2(accM[nt][2] * OUT_SCALE, accM[nt][3] * OUT_SCALE);
    }
}

// ---------------------------------------------------------------------------
// Kernel 2: top-8 + renormalized softmax scores (unchanged, verified)
// ---------------------------------------------------------------------------
__global__ __launch_bounds__(256) void topk_kernel(
    const float* __restrict__ logits,
    float* __restrict__ scores,
    float* __restrict__ indices, int T)
{
    const int warp = (int)((blockIdx.x * blockDim.x + threadIdx.x) >> 5);
    const int lane = threadIdx.x & 31;
    if (warp >= T) return;

    const float* lg = logits + (size_t)warp * E_DIM;
    float v0 = lg[lane];
    float v1 = lg[lane + 32];

    float topv[TOPK];
    int   topi[TOPK];

    #pragma unroll
    for (int r = 0; r < TOPK; r++) {
        bool p   = (v0 >= v1);
        float lv = p ? v0 : v1;
        int   li = p ? lane : lane + 32;
        #pragma unroll
        for (int off = 16; off > 0; off >>= 1) {
            float ov = __shfl_xor_sync(0xffffffffu, lv, off);
            int   oi = __shfl_xor_sync(0xffffffffu, li, off);
            if (ov > lv || (ov == lv && oi < li)) { lv = ov; li = oi; }
        }
        topv[r] = lv; topi[r] = li;
        if (li == lane)           v0 = -INFINITY;
        else if (li == lane + 32) v1 = -INFINITY;
    }

    if (lane == 0) {
        const float m = topv[0];
        float e[TOPK], s = 0.f;
        #pragma unroll
        for (int r = 0; r < TOPK; r++) { e[r] = expf(topv[r] - m); s += e[r]; }
        const float inv = 1.f / s;
        #pragma unroll
        for (int r = 0; r < TOPK; r++) {
            scores [(size_t)warp * TOPK + r] = e[r] * inv;
            indices[(size_t)warp * TOPK + r] = (float)topi[r];
        }
    }
}

// ---------------------------------------------------------------------------
extern "C" void kernel_launch(void* const* d_in, const int* in_sizes, int n_in,
                              void* d_out, int out_size)
{
    const float* hs = (const float*)d_in[0];   // hidden_states [T, 4096]
    const float* w  = (const float*)d_in[1];   // weight        [64, 4096]
    const int T = in_sizes[0] / H_DIM;

    float* out     = (float*)d_out;
    float* logits  = out;
    float* scores  = out + (size_t)T * E_DIM;
    float* indices = scores + (size_t)T * TOPK;

    cudaFuncSetAttribute(router_gemm_tc, cudaFuncAttributeMaxDynamicSharedMemorySize, DYN_SZ);
    router_gemm_tc<<<T / BM, THREADS, DYN_SZ>>>(hs, w, logits);

    const int warps_per_block = 256 / 32;
    const int grid = (T + warps_per_block - 1) / warps_per_block;
    topk_kernel<<<grid, 256>>>(logits, scores, indices, T);
}